// round 15
// baseline (speedup 1.0000x reference)
#include <cuda_runtime.h>
#include <cuda_bf16.h>

#define BATCH   8
#define NNODES  1024
#define IN_DIM  256
#define OUT_DIM 256
#define HEADS   8
#define HDIM    32
#define ROWS    (BATCH * NNODES)   // 8192
#define RPB     4
#define M_MAX   160
#define SC_STR  161

// Scratch (device globals: allocation-free)
__device__ float g_inputs[ROWS * OUT_DIM];
__device__ float g_self [ROWS * HEADS];
__device__ float g_neigh[ROWS * HEADS];

__device__ __forceinline__ unsigned int f2tf32(float f) {
    unsigned int u;
    asm("cvt.rna.tf32.f32 %0, %1;" : "=r"(u) : "f"(f));
    return u;
}

// ---------------- Kernel 1: inputs = X @ W via tf32 mma.sync + fused scores ----
// BM=64, BN=64, BK=32, 128 threads (4 warps in 2x2), warp tile 32x32.
// A stored k-paired: value (r,k) at word (k>>3)*8 + (k&3)*2 + ((k>>2)&1)
// so each thread's (k, k+4) fragment pair is one LDS.64.
#define BM 64
#define BN 64
#define BK 32
#define AS_STR 40
#define BS_STR 72

__global__ __launch_bounds__(128)
void gemm_tf32_kernel(const float* __restrict__ X, const float* __restrict__ W,
                      float* __restrict__ out,
                      float* __restrict__ self_t, float* __restrict__ neigh_t,
                      const float* __restrict__ fc1, const float* __restrict__ fc2) {
    __shared__ __align__(16) unsigned int As[BM][AS_STR];  // 10.2 KB
    __shared__ __align__(16) unsigned int Bs[BK][BS_STR];  // 9.2 KB

    const int t    = threadIdx.x;
    const int warp = t >> 5;
    const int lane = t & 31;
    const int gid  = lane >> 2;
    const int tig  = lane & 3;
    const int wm   = warp & 1;      // m-tile 0..1
    const int wn   = warp >> 1;     // n-tile 0..1
    const int n0 = blockIdx.x * BN;
    const int m0 = blockIdx.y * BM;

    // fused-score coefficients: this warp's 32-col band = one head
    const int h = (n0 + wn * 32) >> 5;
    float f1c[4][2], f2c[4][2];
#pragma unroll
    for (int ni = 0; ni < 4; ni++) {
        const int d = ni * 8 + tig * 2;
        f1c[ni][0] = fc1[h * HDIM + d];     f1c[ni][1] = fc1[h * HDIM + d + 1];
        f2c[ni][0] = fc2[h * HDIM + d];     f2c[ni][1] = fc2[h * HDIM + d + 1];
    }

    float acc[2][4][4];
#pragma unroll
    for (int mi = 0; mi < 2; mi++)
#pragma unroll
        for (int ni = 0; ni < 4; ni++)
#pragma unroll
            for (int q = 0; q < 4; q++) acc[mi][ni][q] = 0.0f;

    for (int k0 = 0; k0 < IN_DIM; k0 += BK) {
        // A tile: 64x32 -> 512 float4 slots, 4 per thread; k-paired store
#pragma unroll
        for (int i = 0; i < 4; i++) {
            int s = t + i * 128;
            int r = s >> 3;
            int c = (s & 7) << 2;
            float4 v = *(const float4*)&X[(m0 + r) * IN_DIM + k0 + c];
            const int base = (c >> 3) * 8 + ((c >> 2) & 1);
            As[r][base + 0] = f2tf32(v.x);
            As[r][base + 2] = f2tf32(v.y);
            As[r][base + 4] = f2tf32(v.z);
            As[r][base + 6] = f2tf32(v.w);
        }
        // B tile: 32x64 -> 512 float4 slots, 4 per thread
#pragma unroll
        for (int i = 0; i < 4; i++) {
            int s = t + i * 128;
            int r = s >> 4;
            int c = (s & 15) << 2;
            uint4 u;
            float4 v = *(const float4*)&W[(k0 + r) * OUT_DIM + n0 + c];
            u.x = f2tf32(v.x); u.y = f2tf32(v.y);
            u.z = f2tf32(v.z); u.w = f2tf32(v.w);
            *(uint4*)&Bs[r][c] = u;
        }
        __syncthreads();

#pragma unroll
        for (int k8 = 0; k8 < 4; k8++) {
            const int kbase = k8 * 8 + tig * 2;
            const int kc    = k8 * 8 + tig;
            uint2 aLo[2], aHi[2];
#pragma unroll
            for (int mi = 0; mi < 2; mi++) {
                const int r = wm * 32 + mi * 16 + gid;
                aLo[mi] = *(const uint2*)&As[r][kbase];      // (a0, a2)
                aHi[mi] = *(const uint2*)&As[r + 8][kbase];  // (a1, a3)
            }
            unsigned int bfr[4][2];
#pragma unroll
            for (int ni = 0; ni < 4; ni++) {
                const int cb = wn * 32 + ni * 8 + gid;
                bfr[ni][0] = Bs[kc][cb];
                bfr[ni][1] = Bs[kc + 4][cb];
            }
#pragma unroll
            for (int mi = 0; mi < 2; mi++)
#pragma unroll
                for (int ni = 0; ni < 4; ni++) {
                    asm volatile(
                        "mma.sync.aligned.m16n8k8.row.col.f32.tf32.tf32.f32 "
                        "{%0,%1,%2,%3}, {%4,%5,%6,%7}, {%8,%9}, {%0,%1,%2,%3};\n"
                        : "+f"(acc[mi][ni][0]), "+f"(acc[mi][ni][1]),
                          "+f"(acc[mi][ni][2]), "+f"(acc[mi][ni][3])
                        : "r"(aLo[mi].x), "r"(aHi[mi].x), "r"(aLo[mi].y), "r"(aHi[mi].y),
                          "r"(bfr[ni][0]), "r"(bfr[ni][1]));
                }
        }
        __syncthreads();
    }

    // ---- epilogue: store + fused score projections ----
#pragma unroll
    for (int mi = 0; mi < 2; mi++) {
        const int row_lo = m0 + wm * 32 + mi * 16 + gid;
        const int row_hi = row_lo + 8;
        float s1_lo = 0.f, s1_hi = 0.f, s2_lo = 0.f, s2_hi = 0.f;
#pragma unroll
        for (int ni = 0; ni < 4; ni++) {
            const int col = n0 + wn * 32 + ni * 8 + tig * 2;
            *(float2*)&out[row_lo * OUT_DIM + col] =
                make_float2(acc[mi][ni][0], acc[mi][ni][1]);
            *(float2*)&out[row_hi * OUT_DIM + col] =
                make_float2(acc[mi][ni][2], acc[mi][ni][3]);
            s1_lo += acc[mi][ni][0] * f1c[ni][0] + acc[mi][ni][1] * f1c[ni][1];
            s1_hi += acc[mi][ni][2] * f1c[ni][0] + acc[mi][ni][3] * f1c[ni][1];
            s2_lo += acc[mi][ni][0] * f2c[ni][0] + acc[mi][ni][1] * f2c[ni][1];
            s2_hi += acc[mi][ni][2] * f2c[ni][0] + acc[mi][ni][3] * f2c[ni][1];
        }
#pragma unroll
        for (int off = 1; off < 4; off <<= 1) {
            s1_lo += __shfl_xor_sync(0xffffffffu, s1_lo, off);
            s1_hi += __shfl_xor_sync(0xffffffffu, s1_hi, off);
            s2_lo += __shfl_xor_sync(0xffffffffu, s2_lo, off);
            s2_hi += __shfl_xor_sync(0xffffffffu, s2_hi, off);
        }
        if (tig == 0) {
            self_t [row_lo * HEADS + h] = s1_lo;
            self_t [row_hi * HEADS + h] = s1_hi;
            neigh_t[row_lo * HEADS + h] = s2_lo;
            neigh_t[row_hi * HEADS + h] = s2_hi;
        }
    }
}

// ---------------- Kernel 2: sparse softmax + aggregation (unchanged) ----------------
__global__ __launch_bounds__(256)
void attn_kernel(const float* __restrict__ A,
                 const float* __restrict__ inp,
                 const float* __restrict__ self_t, const float* __restrict__ neigh_t,
                 float* __restrict__ out) {
    __shared__ float sc[RPB][HEADS][SC_STR];
    __shared__ int   nbr[RPB][M_MAX];
    __shared__ float s_self[RPB][HEADS];
    __shared__ float s_inv[RPB][HEADS];
    __shared__ int   s_cnt[RPB];

    const int blk  = blockIdx.x;
    const int row0 = blk * RPB;
    const int b    = row0 >> 10;
    const int t    = threadIdx.x;

    if (t < RPB) s_cnt[t] = 0;
    if (t < RPB * HEADS) s_self[t >> 3][t & 7] = self_t[(row0 + (t >> 3)) * HEADS + (t & 7)];
    __syncthreads();

    {
        const int r   = t >> 6;
        const int c64 = t & 63;
        const float4* Arow = (const float4*)(A + (long)(row0 + r) * NNODES);
        const float4 v0 = Arow[c64];
        const float4 v1 = Arow[c64 + 64];
        const float4 v2 = Arow[c64 + 128];
        const float4 v3 = Arow[c64 + 192];
        int idx[8]; int c = 0;
        const int b0 = c64 * 4;
        if (v0.x != 0.0f) idx[c++] = b0 + 0;
        if (v0.y != 0.0f) idx[c++] = b0 + 1;
        if (v0.z != 0.0f) idx[c++] = b0 + 2;
        if (v0.w != 0.0f) idx[c++] = b0 + 3;
        if (v1.x != 0.0f) idx[c++] = b0 + 256;
        if (v1.y != 0.0f) idx[c++] = b0 + 257;
        if (v1.z != 0.0f) idx[c++] = b0 + 258;
        if (v1.w != 0.0f) idx[c++] = b0 + 259;
        int idx2[8]; int c2 = 0;
        if (v2.x != 0.0f) idx2[c2++] = b0 + 512;
        if (v2.y != 0.0f) idx2[c2++] = b0 + 513;
        if (v2.z != 0.0f) idx2[c2++] = b0 + 514;
        if (v2.w != 0.0f) idx2[c2++] = b0 + 515;
        if (v3.x != 0.0f) idx2[c2++] = b0 + 768;
        if (v3.y != 0.0f) idx2[c2++] = b0 + 769;
        if (v3.z != 0.0f) idx2[c2++] = b0 + 770;
        if (v3.w != 0.0f) idx2[c2++] = b0 + 771;
        if (c + c2) {
            int p = atomicAdd(&s_cnt[r], c + c2);
            for (int i = 0; i < c; i++)  nbr[r][p + i] = idx[i];
            for (int i = 0; i < c2; i++) nbr[r][p + c + i] = idx2[i];
        }
    }
    __syncthreads();

    {
        const int w = t >> 5, lane = t & 31;
        const float* nb = neigh_t + (long)b * NNODES * HEADS;
#pragma unroll
        for (int p = 0; p < 4; p++) {
            const int pair = w * 4 + p;
            const int pr = pair >> 3, ph = pair & 7;
            const int M = s_cnt[pr];
            const float sw = s_self[pr][ph];
            float mx = -1e30f;
            for (int j = lane; j < M; j += 32) {
                float s = sw + nb[nbr[pr][j] * HEADS + ph];
                s = (s > 0.0f) ? s : 0.01f * s;
                sc[pr][ph][j] = s;
                mx = fmaxf(mx, s);
            }
#pragma unroll
            for (int o = 16; o > 0; o >>= 1) mx = fmaxf(mx, __shfl_xor_sync(0xffffffffu, mx, o));
            float sum = 0.0f;
            for (int j = lane; j < M; j += 32) {
                float e = __expf(sc[pr][ph][j] - mx);
                sc[pr][ph][j] = e;
                sum += e;
            }
#pragma unroll
            for (int o = 16; o > 0; o >>= 1) sum += __shfl_xor_sync(0xffffffffu, sum, o);
            if (lane == 0) s_inv[pr][ph] = 1.0f / sum;
        }
    }
    __syncthreads();

    {
        const int w = t >> 5, lane = t & 31;
        const int r  = w >> 1;
        const int cq = (w & 1) * 32 + lane;
        const int h  = cq >> 3;
        const int M  = s_cnt[r];
        const float* scr = sc[r][h];
        const int* nbrr = nbr[r];
        const float4* inpb = (const float4*)inp + (long)b * NNODES * (OUT_DIM / 4);

        float4 a0 = make_float4(0.f, 0.f, 0.f, 0.f);
        float4 a1 = make_float4(0.f, 0.f, 0.f, 0.f);
        float4 a2 = make_float4(0.f, 0.f, 0.f, 0.f);
        float4 a3 = make_float4(0.f, 0.f, 0.f, 0.f);
        int j = 0;
        for (; j + 3 < M; j += 4) {
            const int i0 = nbrr[j],     i1 = nbrr[j + 1];
            const int i2 = nbrr[j + 2], i3 = nbrr[j + 3];
            const float w0 = scr[j],     w1 = scr[j + 1];
            const float w2 = scr[j + 2], w3 = scr[j + 3];
            const float4 v0 = inpb[i0 * 64 + cq];
            const float4 v1 = inpb[i1 * 64 + cq];
            const float4 v2 = inpb[i2 * 64 + cq];
            const float4 v3 = inpb[i3 * 64 + cq];
            a0.x += w0 * v0.x; a0.y += w0 * v0.y; a0.z += w0 * v0.z; a0.w += w0 * v0.w;
            a1.x += w1 * v1.x; a1.y += w1 * v1.y; a1.z += w1 * v1.z; a1.w += w1 * v1.w;
            a2.x += w2 * v2.x; a2.y += w2 * v2.y; a2.z += w2 * v2.z; a2.w += w2 * v2.w;
            a3.x += w3 * v3.x; a3.y += w3 * v3.y; a3.z += w3 * v3.z; a3.w += w3 * v3.w;
        }
        for (; j < M; j++) {
            const int i0 = nbrr[j];
            const float w0 = scr[j];
            const float4 v0 = inpb[i0 * 64 + cq];
            a0.x += w0 * v0.x; a0.y += w0 * v0.y; a0.z += w0 * v0.z; a0.w += w0 * v0.w;
        }
        const float inv = s_inv[r][h];
        float4 o;
        o.x = fmaxf(((a0.x + a1.x) + (a2.x + a3.x)) * inv, 0.0f);
        o.y = fmaxf(((a0.y + a1.y) + (a2.y + a3.y)) * inv, 0.0f);
        o.z = fmaxf(((a0.z + a1.z) + (a2.z + a3.z)) * inv, 0.0f);
        o.w = fmaxf(((a0.w + a1.w) + (a2.w + a3.w)) * inv, 0.0f);
        *(float4*)&out[(long)(row0 + r) * OUT_DIM + cq * 4] = o;
    }
}

// ---------------- launch ----------------
extern "C" void kernel_launch(void* const* d_in, const int* in_sizes, int n_in,
                              void* d_out, int out_size) {
    const float* A   = (const float*)d_in[0];
    const float* X   = (const float*)d_in[1];
    const float* W   = (const float*)d_in[2];
    const float* fc1 = (const float*)d_in[3];
    const float* fc2 = (const float*)d_in[4];
    float* out = (float*)d_out;

    float *inp, *self_t, *neigh_t;
    cudaGetSymbolAddress((void**)&inp,     g_inputs);
    cudaGetSymbolAddress((void**)&self_t,  g_self);
    cudaGetSymbolAddress((void**)&neigh_t, g_neigh);

    dim3 ggrid(OUT_DIM / BN, ROWS / BM);   // (4, 128) = 512 blocks
    gemm_tf32_kernel<<<ggrid, 128>>>(X, W, inp, self_t, neigh_t, fc1, fc2);
    attn_kernel<<<ROWS / RPB, 256>>>(A, inp, self_t, neigh_t, out);
}

// round 16
// speedup vs baseline: 1.3978x; 1.3978x over previous
#include <cuda_runtime.h>
#include <cuda_bf16.h>

#define BATCH   8
#define NNODES  1024
#define IN_DIM  256
#define OUT_DIM 256
#define HEADS   8
#define HDIM    32
#define ROWS    (BATCH * NNODES)   // 8192
#define RPB     4
#define M_MAX   160
#define SC_STR  161

// Scratch (device globals: allocation-free)
__device__ float g_inputs[ROWS * OUT_DIM];
__device__ float g_self [ROWS * HEADS];
__device__ float g_neigh[ROWS * HEADS];

__device__ __forceinline__ unsigned int f2tf32(float f) {
    unsigned int u;
    asm("cvt.rna.tf32.f32 %0, %1;" : "=r"(u) : "f"(f));
    return u;
}

// ---------------- Kernel 1: inputs = X @ W via tf32 mma.sync ----------------
// BM=64, BN=64, BK=32. 256 threads, 8 warps in 2x4; warp tile 32x16 = 2x2 m16n8k8.
#define BM 64
#define BN 64
#define BK 32
#define AS_STR 36   // uint32 stride; conflict-free fragment reads
#define BS_STR 72

__global__ __launch_bounds__(256)
void gemm_tf32_kernel(const float* __restrict__ X, const float* __restrict__ W,
                      float* __restrict__ out) {
    __shared__ __align__(16) unsigned int As[BM][AS_STR];  // 9.2 KB
    __shared__ __align__(16) unsigned int Bs[BK][BS_STR];  // 9.2 KB

    const int t    = threadIdx.x;
    const int warp = t >> 5;
    const int lane = t & 31;
    const int gid  = lane >> 2;
    const int tig  = lane & 3;
    const int wm   = warp & 1;      // m-tile 0..1 (32 rows)
    const int wn   = warp >> 1;     // n-tile 0..3 (16 cols)
    const int n0 = blockIdx.x * BN;
    const int m0 = blockIdx.y * BM;

    float acc[2][2][4];
#pragma unroll
    for (int mi = 0; mi < 2; mi++)
#pragma unroll
        for (int ni = 0; ni < 2; ni++)
#pragma unroll
            for (int q = 0; q < 4; q++) acc[mi][ni][q] = 0.0f;

    for (int k0 = 0; k0 < IN_DIM; k0 += BK) {
        // A tile: 64x32 -> 512 float4 slots (2 per thread)
#pragma unroll
        for (int i = 0; i < 2; i++) {
            int s = t + i * 256;
            int r = s >> 3;
            int c = (s & 7) << 2;
            float4 v = *(const float4*)&X[(m0 + r) * IN_DIM + k0 + c];
            uint4 u;
            u.x = f2tf32(v.x); u.y = f2tf32(v.y);
            u.z = f2tf32(v.z); u.w = f2tf32(v.w);
            *(uint4*)&As[r][c] = u;
        }
        // B tile: 32x64 -> 512 float4 slots (2 per thread)
#pragma unroll
        for (int i = 0; i < 2; i++) {
            int s = t + i * 256;
            int r = s >> 4;
            int c = (s & 15) << 2;
            float4 v = *(const float4*)&W[(k0 + r) * OUT_DIM + n0 + c];
            uint4 u;
            u.x = f2tf32(v.x); u.y = f2tf32(v.y);
            u.z = f2tf32(v.z); u.w = f2tf32(v.w);
            *(uint4*)&Bs[r][c] = u;
        }
        __syncthreads();

#pragma unroll
        for (int k8 = 0; k8 < 4; k8++) {
            const int kc = k8 * 8 + tig;
            unsigned int a[2][4];
#pragma unroll
            for (int mi = 0; mi < 2; mi++) {
                const int r = wm * 32 + mi * 16 + gid;
                a[mi][0] = As[r][kc];
                a[mi][1] = As[r + 8][kc];
                a[mi][2] = As[r][kc + 4];
                a[mi][3] = As[r + 8][kc + 4];
            }
            unsigned int bfr[2][2];
#pragma unroll
            for (int ni = 0; ni < 2; ni++) {
                const int cb = wn * 16 + ni * 8 + gid;
                bfr[ni][0] = Bs[kc][cb];
                bfr[ni][1] = Bs[kc + 4][cb];
            }
#pragma unroll
            for (int mi = 0; mi < 2; mi++)
#pragma unroll
                for (int ni = 0; ni < 2; ni++) {
                    asm volatile(
                        "mma.sync.aligned.m16n8k8.row.col.f32.tf32.tf32.f32 "
                        "{%0,%1,%2,%3}, {%4,%5,%6,%7}, {%8,%9}, {%0,%1,%2,%3};\n"
                        : "+f"(acc[mi][ni][0]), "+f"(acc[mi][ni][1]),
                          "+f"(acc[mi][ni][2]), "+f"(acc[mi][ni][3])
                        : "r"(a[mi][0]), "r"(a[mi][1]), "r"(a[mi][2]), "r"(a[mi][3]),
                          "r"(bfr[ni][0]), "r"(bfr[ni][1]));
                }
        }
        __syncthreads();
    }

    // epilogue
#pragma unroll
    for (int mi = 0; mi < 2; mi++) {
        const int row = m0 + wm * 32 + mi * 16 + gid;
#pragma unroll
        for (int ni = 0; ni < 2; ni++) {
            const int col = n0 + wn * 16 + ni * 8 + tig * 2;
            *(float2*)&out[row * OUT_DIM + col] =
                make_float2(acc[mi][ni][0], acc[mi][ni][1]);
            *(float2*)&out[(row + 8) * OUT_DIM + col] =
                make_float2(acc[mi][ni][2], acc[mi][ni][3]);
        }
    }
}

// ---------------- Kernel 2: score projections (also prefetches g_inputs into L2) ----
__global__ __launch_bounds__(256)
void scores_kernel(const float* __restrict__ inp,
                   const float* __restrict__ fc1, const float* __restrict__ fc2,
                   float* __restrict__ self_t, float* __restrict__ neigh_t) {
    const int bn = blockIdx.x;
    const int t  = threadIdx.x;
    const int h  = t >> 5;
    const int d  = t & 31;
    float v  = inp[bn * OUT_DIM + t];
    float s1 = v * fc1[h * HDIM + d];
    float s2 = v * fc2[h * HDIM + d];
#pragma unroll
    for (int o = 16; o > 0; o >>= 1) {
        s1 += __shfl_xor_sync(0xffffffffu, s1, o);
        s2 += __shfl_xor_sync(0xffffffffu, s2, o);
    }
    if (d == 0) {
        self_t [bn * HEADS + h] = s1;
        neigh_t[bn * HEADS + h] = s2;
    }
}

// ---------------- Kernel 3: sparse softmax + aggregation (R10/R14 exact) ----------------
__global__ __launch_bounds__(256)
void attn_kernel(const float* __restrict__ A,
                 const float* __restrict__ inp,
                 const float* __restrict__ self_t, const float* __restrict__ neigh_t,
                 float* __restrict__ out) {
    __shared__ float sc[RPB][HEADS][SC_STR];
    __shared__ int   nbr[RPB][M_MAX];
    __shared__ float s_self[RPB][HEADS];
    __shared__ float s_inv[RPB][HEADS];
    __shared__ int   s_cnt[RPB];

    const int blk  = blockIdx.x;
    const int row0 = blk * RPB;
    const int b    = row0 >> 10;
    const int t    = threadIdx.x;

    if (t < RPB) s_cnt[t] = 0;
    if (t < RPB * HEADS) s_self[t >> 3][t & 7] = self_t[(row0 + (t >> 3)) * HEADS + (t & 7)];
    __syncthreads();

    {
        const int r   = t >> 6;
        const int c64 = t & 63;
        const float4* Arow = (const float4*)(A + (long)(row0 + r) * NNODES);
        const float4 v0 = Arow[c64];
        const float4 v1 = Arow[c64 + 64];
        const float4 v2 = Arow[c64 + 128];
        const float4 v3 = Arow[c64 + 192];
        int idx[8]; int c = 0;
        const int b0 = c64 * 4;
        if (v0.x != 0.0f) idx[c++] = b0 + 0;
        if (v0.y != 0.0f) idx[c++] = b0 + 1;
        if (v0.z != 0.0f) idx[c++] = b0 + 2;
        if (v0.w != 0.0f) idx[c++] = b0 + 3;
        if (v1.x != 0.0f) idx[c++] = b0 + 256;
        if (v1.y != 0.0f) idx[c++] = b0 + 257;
        if (v1.z != 0.0f) idx[c++] = b0 + 258;
        if (v1.w != 0.0f) idx[c++] = b0 + 259;
        int idx2[8]; int c2 = 0;
        if (v2.x != 0.0f) idx2[c2++] = b0 + 512;
        if (v2.y != 0.0f) idx2[c2++] = b0 + 513;
        if (v2.z != 0.0f) idx2[c2++] = b0 + 514;
        if (v2.w != 0.0f) idx2[c2++] = b0 + 515;
        if (v3.x != 0.0f) idx2[c2++] = b0 + 768;
        if (v3.y != 0.0f) idx2[c2++] = b0 + 769;
        if (v3.z != 0.0f) idx2[c2++] = b0 + 770;
        if (v3.w != 0.0f) idx2[c2++] = b0 + 771;
        if (c + c2) {
            int p = atomicAdd(&s_cnt[r], c + c2);
            for (int i = 0; i < c; i++)  nbr[r][p + i] = idx[i];
            for (int i = 0; i < c2; i++) nbr[r][p + c + i] = idx2[i];
        }
    }
    __syncthreads();

    {
        const int w = t >> 5, lane = t & 31;
        const float* nb = neigh_t + (long)b * NNODES * HEADS;
#pragma unroll
        for (int p = 0; p < 4; p++) {
            const int pair = w * 4 + p;
            const int pr = pair >> 3, ph = pair & 7;
            const int M = s_cnt[pr];
            const float sw = s_self[pr][ph];
            float mx = -1e30f;
            for (int j = lane; j < M; j += 32) {
                float s = sw + nb[nbr[pr][j] * HEADS + ph];
                s = (s > 0.0f) ? s : 0.01f * s;
                sc[pr][ph][j] = s;
                mx = fmaxf(mx, s);
            }
#pragma unroll
            for (int o = 16; o > 0; o >>= 1) mx = fmaxf(mx, __shfl_xor_sync(0xffffffffu, mx, o));
            float sum = 0.0f;
            for (int j = lane; j < M; j += 32) {
                float e = __expf(sc[pr][ph][j] - mx);
                sc[pr][ph][j] = e;
                sum += e;
            }
#pragma unroll
            for (int o = 16; o > 0; o >>= 1) sum += __shfl_xor_sync(0xffffffffu, sum, o);
            if (lane == 0) s_inv[pr][ph] = 1.0f / sum;
        }
    }
    __syncthreads();

    {
        const int w = t >> 5, lane = t & 31;
        const int r  = w >> 1;
        const int cq = (w & 1) * 32 + lane;
        const int h  = cq >> 3;
        const int M  = s_cnt[r];
        const float* scr = sc[r][h];
        const int* nbrr = nbr[r];
        const float4* inpb = (const float4*)inp + (long)b * NNODES * (OUT_DIM / 4);

        float4 a0 = make_float4(0.f, 0.f, 0.f, 0.f);
        float4 a1 = make_float4(0.f, 0.f, 0.f, 0.f);
        float4 a2 = make_float4(0.f, 0.f, 0.f, 0.f);
        float4 a3 = make_float4(0.f, 0.f, 0.f, 0.f);
        int j = 0;
        for (; j + 3 < M; j += 4) {
            const int i0 = nbrr[j],     i1 = nbrr[j + 1];
            const int i2 = nbrr[j + 2], i3 = nbrr[j + 3];
            const float w0 = scr[j],     w1 = scr[j + 1];
            const float w2 = scr[j + 2], w3 = scr[j + 3];
            const float4 v0 = inpb[i0 * 64 + cq];
            const float4 v1 = inpb[i1 * 64 + cq];
            const float4 v2 = inpb[i2 * 64 + cq];
            const float4 v3 = inpb[i3 * 64 + cq];
            a0.x += w0 * v0.x; a0.y += w0 * v0.y; a0.z += w0 * v0.z; a0.w += w0 * v0.w;
            a1.x += w1 * v1.x; a1.y += w1 * v1.y; a1.z += w1 * v1.z; a1.w += w1 * v1.w;
            a2.x += w2 * v2.x; a2.y += w2 * v2.y; a2.z += w2 * v2.z; a2.w += w2 * v2.w;
            a3.x += w3 * v3.x; a3.y += w3 * v3.y; a3.z += w3 * v3.z; a3.w += w3 * v3.w;
        }
        for (; j < M; j++) {
            const int i0 = nbrr[j];
            const float w0 = scr[j];
            const float4 v0 = inpb[i0 * 64 + cq];
            a0.x += w0 * v0.x; a0.y += w0 * v0.y; a0.z += w0 * v0.z; a0.w += w0 * v0.w;
        }
        const float inv = s_inv[r][h];
        float4 o;
        o.x = fmaxf(((a0.x + a1.x) + (a2.x + a3.x)) * inv, 0.0f);
        o.y = fmaxf(((a0.y + a1.y) + (a2.y + a3.y)) * inv, 0.0f);
        o.z = fmaxf(((a0.z + a1.z) + (a2.z + a3.z)) * inv, 0.0f);
        o.w = fmaxf(((a0.w + a1.w) + (a2.w + a3.w)) * inv, 0.0f);
        *(float4*)&out[(long)(row0 + r) * OUT_DIM + cq * 4] = o;
    }
}

// ---------------- launch ----------------
extern "C" void kernel_launch(void* const* d_in, const int* in_sizes, int n_in,
                              void* d_out, int out_size) {
    const float* A   = (const float*)d_in[0];
    const float* X   = (const float*)d_in[1];
    const float* W   = (const float*)d_in[2];
    const float* fc1 = (const float*)d_in[3];
    const float* fc2 = (const float*)d_in[4];
    float* out = (float*)d_out;

    float *inp, *self_t, *neigh_t;
    cudaGetSymbolAddress((void**)&inp,     g_inputs);
    cudaGetSymbolAddress((void**)&self_t,  g_self);
    cudaGetSymbolAddress((void**)&neigh_t, g_neigh);

    dim3 ggrid(OUT_DIM / BN, ROWS / BM);   // (4, 128) = 512 blocks
    gemm_tf32_kernel<<<ggrid, 256>>>(X, W, inp);
    scores_kernel<<<ROWS, 256>>>(inp, fc1, fc2, self_t, neigh_t);
    attn_kernel<<<ROWS / RPB, 256>>>(A, inp, self_t, neigh_t, out);
}